// round 1
// baseline (speedup 1.0000x reference)
#include <cuda_runtime.h>
#include <cuda_bf16.h>
#include <math.h>

#define D_MODEL 1024
#define NUM_HEADS 16
#define DK 64
#define BATCH 2
#define SEQ 2048
#define MROWS (BATCH * SEQ)   // 4096

// ---------------- scratch (static device globals; no allocations) ----------
__device__ float g_qh[BATCH * NUM_HEADS * SEQ * DK];   // [B,H,S,64]
__device__ float g_kh[BATCH * NUM_HEADS * SEQ * DK];
__device__ float g_vh[BATCH * NUM_HEADS * SEQ * DK];
__device__ float g_ctx[MROWS * D_MODEL];               // [B*S, 1024]

// ---------------------------------------------------------------------------
// Tiled SGEMM: out[m,n] = (sum_k A[m,k] * W[n,k] + bias[n]) * scale
// A: [4096,1024] row-major, W: [1024,1024] row-major (row n = output feature)
// BM=BN=128, BK=16, 256 threads, 8x8 per thread.
// HEAD_LAYOUT: write to [B,H,S,DK] instead of [M,N].
// ---------------------------------------------------------------------------
template <bool HEAD_LAYOUT>
__global__ __launch_bounds__(256, 2)
void gemm_bias_kernel(const float* __restrict__ A,
                      const float* __restrict__ W,
                      const float* __restrict__ bias,
                      float* __restrict__ out,
                      float scale)
{
    __shared__ float As[16 * 132];  // As[k][m], padded stride 132
    __shared__ float Bs[16 * 132];  // Bs[k][n]

    const int tid = threadIdx.x;
    const int tx = tid & 15;        // n-dim
    const int ty = tid >> 4;        // m-dim
    const int blockM = blockIdx.y * 128;
    const int blockN = blockIdx.x * 128;

    float acc[8][8];
#pragma unroll
    for (int i = 0; i < 8; i++)
#pragma unroll
        for (int j = 0; j < 8; j++) acc[i][j] = 0.f;

    for (int kt = 0; kt < D_MODEL / 16; kt++) {
        const int k0 = kt * 16;
        // load A tile 128x16 -> As[k][m] (transposed), 2 float4 per thread
#pragma unroll
        for (int it = 0; it < 2; it++) {
            int idx = tid * 2 + it;        // 0..511
            int row = idx >> 2;            // 0..127
            int c4  = idx & 3;             // 0..3
            float4 v = *reinterpret_cast<const float4*>(
                A + (size_t)(blockM + row) * D_MODEL + k0 + c4 * 4);
            As[(c4 * 4 + 0) * 132 + row] = v.x;
            As[(c4 * 4 + 1) * 132 + row] = v.y;
            As[(c4 * 4 + 2) * 132 + row] = v.z;
            As[(c4 * 4 + 3) * 132 + row] = v.w;
            float4 w = *reinterpret_cast<const float4*>(
                W + (size_t)(blockN + row) * D_MODEL + k0 + c4 * 4);
            Bs[(c4 * 4 + 0) * 132 + row] = w.x;
            Bs[(c4 * 4 + 1) * 132 + row] = w.y;
            Bs[(c4 * 4 + 2) * 132 + row] = w.z;
            Bs[(c4 * 4 + 3) * 132 + row] = w.w;
        }
        __syncthreads();

#pragma unroll
        for (int kk = 0; kk < 16; kk++) {
            float4 a0 = *reinterpret_cast<const float4*>(&As[kk * 132 + ty * 8]);
            float4 a1 = *reinterpret_cast<const float4*>(&As[kk * 132 + ty * 8 + 4]);
            float4 b0 = *reinterpret_cast<const float4*>(&Bs[kk * 132 + tx * 8]);
            float4 b1 = *reinterpret_cast<const float4*>(&Bs[kk * 132 + tx * 8 + 4]);
            float a[8] = {a0.x, a0.y, a0.z, a0.w, a1.x, a1.y, a1.z, a1.w};
            float b[8] = {b0.x, b0.y, b0.z, b0.w, b1.x, b1.y, b1.z, b1.w};
#pragma unroll
            for (int i = 0; i < 8; i++)
#pragma unroll
                for (int j = 0; j < 8; j++) acc[i][j] += a[i] * b[j];
        }
        __syncthreads();
    }

    // epilogue
#pragma unroll
    for (int i = 0; i < 8; i++) {
        const int m = blockM + ty * 8 + i;
#pragma unroll
        for (int j = 0; j < 8; j++) {
            const int n = blockN + tx * 8 + j;
            float v = (acc[i][j] + bias[n]) * scale;
            if (HEAD_LAYOUT) {
                const int b = m >> 11;          // m / 2048
                const int s = m & 2047;
                const int h = n >> 6;           // n / 64
                const int d = n & 63;
                out[(((size_t)(b * NUM_HEADS + h) * SEQ + s) * DK) + d] = v;
            } else {
                out[(size_t)m * D_MODEL + n] = v;
            }
        }
    }
}

// ---------------------------------------------------------------------------
// Fused flash-style attention (fp32). One CTA per (qblock of 64, head, batch).
// 256 threads. Per 64-key tile:
//  phase A: S = Q K^T (64x64x64 mini-GEMM from transposed smem), mask applied
//  phase B: online softmax (4 lanes per row) + P*V accumulate
// Scale 1/sqrt(64) already folded into Q at projection time.
// ---------------------------------------------------------------------------
__global__ __launch_bounds__(256, 3)
void flash_attn_kernel(const float* __restrict__ qh,
                       const float* __restrict__ kh,
                       const float* __restrict__ vh,
                       const int*   __restrict__ mask,
                       float* __restrict__ ctx)
{
    extern __shared__ float smem[];
    float* Qs = smem;                 // [64 dims][65] transposed: Qs[d*65 + r]
    float* Ks = Qs + 64 * 65;         // [64 dims][65] transposed: Ks[d*65 + j]
    float* Ss = Ks + 64 * 65;         // [64 rows][65]: Ss[r*65 + j]
    float* Vs = Ss + 64 * 65;         // [64 keys][64]: Vs[j*64 + d]
    int*   maskS = reinterpret_cast<int*>(Vs + 64 * 64);  // [64]

    const int tid = threadIdx.x;
    const int b = blockIdx.z;
    const int h = blockIdx.y;
    const int q0 = blockIdx.x * 64;

    const float* qptr = qh + ((size_t)(b * NUM_HEADS + h) * SEQ + q0) * DK;
    const float* kbase_ptr = kh + (size_t)(b * NUM_HEADS + h) * SEQ * DK;
    const float* vbase_ptr = vh + (size_t)(b * NUM_HEADS + h) * SEQ * DK;

    // load Q tile transposed (64 rows x 64 dims -> Qs[d][r])
#pragma unroll
    for (int it = 0; it < 4; it++) {
        int idx = tid + it * 256;     // 0..1023 over float4 units
        int r  = idx >> 4;            // 0..63
        int c4 = idx & 15;            // 0..15
        float4 v = *reinterpret_cast<const float4*>(qptr + r * DK + c4 * 4);
        Qs[(c4 * 4 + 0) * 65 + r] = v.x;
        Qs[(c4 * 4 + 1) * 65 + r] = v.y;
        Qs[(c4 * 4 + 2) * 65 + r] = v.z;
        Qs[(c4 * 4 + 3) * 65 + r] = v.w;
    }

    // per-thread softmax state: 4 threads per row
    const int row  = tid >> 2;        // 0..63
    const int sub  = tid & 3;         // 0..3
    const int cbase = sub * 16;
    float mval = -INFINITY;
    float lval = 0.f;
    float o[16];
#pragma unroll
    for (int c = 0; c < 16; c++) o[c] = 0.f;

    // phase-A thread mapping
    const int tx = tid & 15;          // key cols
    const int ty = tid >> 4;          // q rows
    const int r0 = ty * 4;
    const int j0 = tx * 4;

    for (int kt = 0; kt < SEQ / 64; kt++) {
        const int kpos0 = kt * 64;
        const float* kptr = kbase_ptr + (size_t)kpos0 * DK;
        const float* vptr = vbase_ptr + (size_t)kpos0 * DK;

        // load K tile (transposed) and V tile (natural)
#pragma unroll
        for (int it = 0; it < 4; it++) {
            int idx = tid + it * 256;
            int r  = idx >> 4;
            int c4 = idx & 15;
            float4 kv = *reinterpret_cast<const float4*>(kptr + r * DK + c4 * 4);
            Ks[(c4 * 4 + 0) * 65 + r] = kv.x;
            Ks[(c4 * 4 + 1) * 65 + r] = kv.y;
            Ks[(c4 * 4 + 2) * 65 + r] = kv.z;
            Ks[(c4 * 4 + 3) * 65 + r] = kv.w;
            float4 vv = *reinterpret_cast<const float4*>(vptr + r * DK + c4 * 4);
            *reinterpret_cast<float4*>(&Vs[r * 64 + c4 * 4]) = vv;
        }
        if (tid < 64) maskS[tid] = mask[b * SEQ + kpos0 + tid];
        __syncthreads();

        // ---- phase A: scores 4x4 per thread ----
        float cc[4][4];
#pragma unroll
        for (int i = 0; i < 4; i++)
#pragma unroll
            for (int j = 0; j < 4; j++) cc[i][j] = 0.f;

#pragma unroll 8
        for (int d = 0; d < 64; d++) {
            float a0 = Qs[d * 65 + r0 + 0];
            float a1 = Qs[d * 65 + r0 + 1];
            float a2 = Qs[d * 65 + r0 + 2];
            float a3 = Qs[d * 65 + r0 + 3];
            float b0 = Ks[d * 65 + j0 + 0];
            float b1 = Ks[d * 65 + j0 + 1];
            float b2 = Ks[d * 65 + j0 + 2];
            float b3 = Ks[d * 65 + j0 + 3];
            cc[0][0] += a0 * b0; cc[0][1] += a0 * b1; cc[0][2] += a0 * b2; cc[0][3] += a0 * b3;
            cc[1][0] += a1 * b0; cc[1][1] += a1 * b1; cc[1][2] += a1 * b2; cc[1][3] += a1 * b3;
            cc[2][0] += a2 * b0; cc[2][1] += a2 * b1; cc[2][2] += a2 * b2; cc[2][3] += a2 * b3;
            cc[3][0] += a3 * b0; cc[3][1] += a3 * b1; cc[3][2] += a3 * b2; cc[3][3] += a3 * b3;
        }
#pragma unroll
        for (int j = 0; j < 4; j++) {
            const int jj = j0 + j;
            const bool keep = (maskS[jj] != 0);
#pragma unroll
            for (int i = 0; i < 4; i++) {
                Ss[(r0 + i) * 65 + jj] = keep ? cc[i][j] : -1e9f;
            }
        }
        __syncthreads();

        // ---- phase B: online softmax + P*V ----
        float tmax = -INFINITY;
#pragma unroll
        for (int t = 0; t < 16; t++) tmax = fmaxf(tmax, Ss[row * 65 + cbase + t]);
        tmax = fmaxf(tmax, __shfl_xor_sync(0xffffffffu, tmax, 1));
        tmax = fmaxf(tmax, __shfl_xor_sync(0xffffffffu, tmax, 2));

        const float m_new = fmaxf(mval, tmax);
        const float alpha = __expf(mval - m_new);

        float psum = 0.f;
#pragma unroll
        for (int t = 0; t < 16; t++) {
            float p = __expf(Ss[row * 65 + cbase + t] - m_new);
            Ss[row * 65 + cbase + t] = p;
            psum += p;
        }
        psum += __shfl_xor_sync(0xffffffffu, psum, 1);
        psum += __shfl_xor_sync(0xffffffffu, psum, 2);
        lval = lval * alpha + psum;
        mval = m_new;

#pragma unroll
        for (int c = 0; c < 16; c++) o[c] *= alpha;
        __syncwarp();

#pragma unroll 8
        for (int j = 0; j < 64; j++) {
            const float p = Ss[row * 65 + j];
            const float* vrow = &Vs[j * 64 + cbase];
            float4 v0 = *reinterpret_cast<const float4*>(vrow + 0);
            float4 v1 = *reinterpret_cast<const float4*>(vrow + 4);
            float4 v2 = *reinterpret_cast<const float4*>(vrow + 8);
            float4 v3 = *reinterpret_cast<const float4*>(vrow + 12);
            o[0] += p * v0.x;  o[1] += p * v0.y;  o[2] += p * v0.z;  o[3] += p * v0.w;
            o[4] += p * v1.x;  o[5] += p * v1.y;  o[6] += p * v1.z;  o[7] += p * v1.w;
            o[8] += p * v2.x;  o[9] += p * v2.y;  o[10] += p * v2.z; o[11] += p * v2.w;
            o[12] += p * v3.x; o[13] += p * v3.y; o[14] += p * v3.z; o[15] += p * v3.w;
        }
        __syncthreads();
    }

    // write ctx[B*S, 1024] (heads back in column blocks)
    const float inv = 1.f / lval;
    float* optr = ctx + ((size_t)(b * SEQ + q0 + row) * D_MODEL) + h * DK + cbase;
#pragma unroll
    for (int c4 = 0; c4 < 4; c4++) {
        float4 v;
        v.x = o[c4 * 4 + 0] * inv;
        v.y = o[c4 * 4 + 1] * inv;
        v.z = o[c4 * 4 + 2] * inv;
        v.w = o[c4 * 4 + 3] * inv;
        *reinterpret_cast<float4*>(optr + c4 * 4) = v;
    }
}

// ---------------------------------------------------------------------------
extern "C" void kernel_launch(void* const* d_in, const int* in_sizes, int n_in,
                              void* d_out, int out_size)
{
    const float* q    = (const float*)d_in[0];
    const float* k    = (const float*)d_in[1];
    const float* v    = (const float*)d_in[2];
    const int*   mask = (const int*)  d_in[3];
    const float* Wq   = (const float*)d_in[4];
    const float* bq   = (const float*)d_in[5];
    const float* Wk   = (const float*)d_in[6];
    const float* bk   = (const float*)d_in[7];
    const float* Wv   = (const float*)d_in[8];
    const float* bv   = (const float*)d_in[9];
    const float* Wo   = (const float*)d_in[10];
    const float* bo   = (const float*)d_in[11];
    float* out = (float*)d_out;

    float *qh, *kh, *vh, *ctx;
    cudaGetSymbolAddress((void**)&qh,  g_qh);
    cudaGetSymbolAddress((void**)&kh,  g_kh);
    cudaGetSymbolAddress((void**)&vh,  g_vh);
    cudaGetSymbolAddress((void**)&ctx, g_ctx);

    dim3 gemm_grid(D_MODEL / 128, MROWS / 128);   // (8, 32)
    const float qscale = 0.125f;                   // 1/sqrt(64)

    gemm_bias_kernel<true><<<gemm_grid, 256>>>(q, Wq, bq, qh, qscale);
    gemm_bias_kernel<true><<<gemm_grid, 256>>>(k, Wk, bk, kh, 1.0f);
    gemm_bias_kernel<true><<<gemm_grid, 256>>>(v, Wv, bv, vh, 1.0f);

    // flash attention
    size_t smem_bytes = (64 * 65 * 3 + 64 * 64) * sizeof(float) + 64 * sizeof(int);
    cudaFuncSetAttribute(flash_attn_kernel,
                         cudaFuncAttributeMaxDynamicSharedMemorySize,
                         (int)smem_bytes);
    dim3 attn_grid(SEQ / 64, NUM_HEADS, BATCH);    // (32,16,2)
    flash_attn_kernel<<<attn_grid, 256, smem_bytes>>>(qh, kh, vh, mask, ctx);

    gemm_bias_kernel<false><<<gemm_grid, 256>>>(ctx, Wo, bo, out, 1.0f);
}

// round 2
// speedup vs baseline: 1.0019x; 1.0019x over previous
#include <cuda_runtime.h>
#include <cuda_bf16.h>
#include <math.h>

#define D_MODEL 1024
#define NUM_HEADS 16
#define DK 64
#define BATCH 2
#define SEQ 2048
#define MROWS (BATCH * SEQ)   // 4096

// ---------------- scratch (static device globals; no allocations) ----------
__device__ float g_qh[BATCH * NUM_HEADS * SEQ * DK];   // [B,H,S,64]
__device__ float g_kh[BATCH * NUM_HEADS * SEQ * DK];
__device__ float g_vh[BATCH * NUM_HEADS * SEQ * DK];
__device__ float g_ctx[MROWS * D_MODEL];               // [B*S, 1024]

// ---------------------------------------------------------------------------
// Tiled SGEMM: out[m,n] = (sum_k A[m,k] * W[n,k] + bias[n]) * scale
// A: [4096,1024] row-major, W: [1024,1024] row-major (row n = output feature)
// BM=BN=128, BK=16, 256 threads, 8x8 per thread.
// HEAD_LAYOUT: write to [B,H,S,DK] instead of [M,N].
// ---------------------------------------------------------------------------
template <bool HEAD_LAYOUT>
__global__ __launch_bounds__(256, 2)
void gemm_bias_kernel(const float* __restrict__ A,
                      const float* __restrict__ W,
                      const float* __restrict__ bias,
                      float* __restrict__ out,
                      float scale)
{
    __shared__ float As[16 * 132];  // As[k][m], padded stride 132
    __shared__ float Bs[16 * 132];  // Bs[k][n]

    const int tid = threadIdx.x;
    const int tx = tid & 15;        // n-dim
    const int ty = tid >> 4;        // m-dim
    const int blockM = blockIdx.y * 128;
    const int blockN = blockIdx.x * 128;

    float acc[8][8];
#pragma unroll
    for (int i = 0; i < 8; i++)
#pragma unroll
        for (int j = 0; j < 8; j++) acc[i][j] = 0.f;

    for (int kt = 0; kt < D_MODEL / 16; kt++) {
        const int k0 = kt * 16;
        // load A tile 128x16 -> As[k][m] (transposed), 2 float4 per thread
#pragma unroll
        for (int it = 0; it < 2; it++) {
            int idx = tid * 2 + it;        // 0..511
            int row = idx >> 2;            // 0..127
            int c4  = idx & 3;             // 0..3
            float4 v = *reinterpret_cast<const float4*>(
                A + (size_t)(blockM + row) * D_MODEL + k0 + c4 * 4);
            As[(c4 * 4 + 0) * 132 + row] = v.x;
            As[(c4 * 4 + 1) * 132 + row] = v.y;
            As[(c4 * 4 + 2) * 132 + row] = v.z;
            As[(c4 * 4 + 3) * 132 + row] = v.w;
            float4 w = *reinterpret_cast<const float4*>(
                W + (size_t)(blockN + row) * D_MODEL + k0 + c4 * 4);
            Bs[(c4 * 4 + 0) * 132 + row] = w.x;
            Bs[(c4 * 4 + 1) * 132 + row] = w.y;
            Bs[(c4 * 4 + 2) * 132 + row] = w.z;
            Bs[(c4 * 4 + 3) * 132 + row] = w.w;
        }
        __syncthreads();

#pragma unroll
        for (int kk = 0; kk < 16; kk++) {
            float4 a0 = *reinterpret_cast<const float4*>(&As[kk * 132 + ty * 8]);
            float4 a1 = *reinterpret_cast<const float4*>(&As[kk * 132 + ty * 8 + 4]);
            float4 b0 = *reinterpret_cast<const float4*>(&Bs[kk * 132 + tx * 8]);
            float4 b1 = *reinterpret_cast<const float4*>(&Bs[kk * 132 + tx * 8 + 4]);
            float a[8] = {a0.x, a0.y, a0.z, a0.w, a1.x, a1.y, a1.z, a1.w};
            float b[8] = {b0.x, b0.y, b0.z, b0.w, b1.x, b1.y, b1.z, b1.w};
#pragma unroll
            for (int i = 0; i < 8; i++)
#pragma unroll
                for (int j = 0; j < 8; j++) acc[i][j] += a[i] * b[j];
        }
        __syncthreads();
    }

    // epilogue
#pragma unroll
    for (int i = 0; i < 8; i++) {
        const int m = blockM + ty * 8 + i;
#pragma unroll
        for (int j = 0; j < 8; j++) {
            const int n = blockN + tx * 8 + j;
            float v = (acc[i][j] + bias[n]) * scale;
            if (HEAD_LAYOUT) {
                const int b = m >> 11;          // m / 2048
                const int s = m & 2047;
                const int h = n >> 6;           // n / 64
                const int d = n & 63;
                out[(((size_t)(b * NUM_HEADS + h) * SEQ + s) * DK) + d] = v;
            } else {
                out[(size_t)m * D_MODEL + n] = v;
            }
        }
    }
}

// ---------------------------------------------------------------------------
// Fused flash-style attention (fp32). One CTA per (qblock of 64, head, batch).
// 256 threads. Per 64-key tile:
//  phase A: S = Q K^T (64x64x64 mini-GEMM from transposed smem), mask applied
//  phase B: online softmax (4 lanes per row) + P*V accumulate
// Scale 1/sqrt(64) already folded into Q at projection time.
// ---------------------------------------------------------------------------
__global__ __launch_bounds__(256, 3)
void flash_attn_kernel(const float* __restrict__ qh,
                       const float* __restrict__ kh,
                       const float* __restrict__ vh,
                       const int*   __restrict__ mask,
                       float* __restrict__ ctx)
{
    extern __shared__ float smem[];
    float* Qs = smem;                 // [64 dims][65] transposed: Qs[d*65 + r]
    float* Ks = Qs + 64 * 65;         // [64 dims][65] transposed: Ks[d*65 + j]
    float* Ss = Ks + 64 * 65;         // [64 rows][65]: Ss[r*65 + j]
    float* Vs = Ss + 64 * 65;         // [64 keys][64]: Vs[j*64 + d]
    int*   maskS = reinterpret_cast<int*>(Vs + 64 * 64);  // [64]

    const int tid = threadIdx.x;
    const int b = blockIdx.z;
    const int h = blockIdx.y;
    const int q0 = blockIdx.x * 64;

    const float* qptr = qh + ((size_t)(b * NUM_HEADS + h) * SEQ + q0) * DK;
    const float* kbase_ptr = kh + (size_t)(b * NUM_HEADS + h) * SEQ * DK;
    const float* vbase_ptr = vh + (size_t)(b * NUM_HEADS + h) * SEQ * DK;

    // load Q tile transposed (64 rows x 64 dims -> Qs[d][r])
#pragma unroll
    for (int it = 0; it < 4; it++) {
        int idx = tid + it * 256;     // 0..1023 over float4 units
        int r  = idx >> 4;            // 0..63
        int c4 = idx & 15;            // 0..15
        float4 v = *reinterpret_cast<const float4*>(qptr + r * DK + c4 * 4);
        Qs[(c4 * 4 + 0) * 65 + r] = v.x;
        Qs[(c4 * 4 + 1) * 65 + r] = v.y;
        Qs[(c4 * 4 + 2) * 65 + r] = v.z;
        Qs[(c4 * 4 + 3) * 65 + r] = v.w;
    }

    // per-thread softmax state: 4 threads per row
    const int row  = tid >> 2;        // 0..63
    const int sub  = tid & 3;         // 0..3
    const int cbase = sub * 16;
    float mval = -INFINITY;
    float lval = 0.f;
    float o[16];
#pragma unroll
    for (int c = 0; c < 16; c++) o[c] = 0.f;

    // phase-A thread mapping
    const int tx = tid & 15;          // key cols
    const int ty = tid >> 4;          // q rows
    const int r0 = ty * 4;
    const int j0 = tx * 4;

    for (int kt = 0; kt < SEQ / 64; kt++) {
        const int kpos0 = kt * 64;
        const float* kptr = kbase_ptr + (size_t)kpos0 * DK;
        const float* vptr = vbase_ptr + (size_t)kpos0 * DK;

        // load K tile (transposed) and V tile (natural)
#pragma unroll
        for (int it = 0; it < 4; it++) {
            int idx = tid + it * 256;
            int r  = idx >> 4;
            int c4 = idx & 15;
            float4 kv = *reinterpret_cast<const float4*>(kptr + r * DK + c4 * 4);
            Ks[(c4 * 4 + 0) * 65 + r] = kv.x;
            Ks[(c4 * 4 + 1) * 65 + r] = kv.y;
            Ks[(c4 * 4 + 2) * 65 + r] = kv.z;
            Ks[(c4 * 4 + 3) * 65 + r] = kv.w;
            float4 vv = *reinterpret_cast<const float4*>(vptr + r * DK + c4 * 4);
            *reinterpret_cast<float4*>(&Vs[r * 64 + c4 * 4]) = vv;
        }
        if (tid < 64) maskS[tid] = mask[b * SEQ + kpos0 + tid];
        __syncthreads();

        // ---- phase A: scores 4x4 per thread ----
        float cc[4][4];
#pragma unroll
        for (int i = 0; i < 4; i++)
#pragma unroll
            for (int j = 0; j < 4; j++) cc[i][j] = 0.f;

#pragma unroll 8
        for (int d = 0; d < 64; d++) {
            float a0 = Qs[d * 65 + r0 + 0];
            float a1 = Qs[d * 65 + r0 + 1];
            float a2 = Qs[d * 65 + r0 + 2];
            float a3 = Qs[d * 65 + r0 + 3];
            float b0 = Ks[d * 65 + j0 + 0];
            float b1 = Ks[d * 65 + j0 + 1];
            float b2 = Ks[d * 65 + j0 + 2];
            float b3 = Ks[d * 65 + j0 + 3];
            cc[0][0] += a0 * b0; cc[0][1] += a0 * b1; cc[0][2] += a0 * b2; cc[0][3] += a0 * b3;
            cc[1][0] += a1 * b0; cc[1][1] += a1 * b1; cc[1][2] += a1 * b2; cc[1][3] += a1 * b3;
            cc[2][0] += a2 * b0; cc[2][1] += a2 * b1; cc[2][2] += a2 * b2; cc[2][3] += a2 * b3;
            cc[3][0] += a3 * b0; cc[3][1] += a3 * b1; cc[3][2] += a3 * b2; cc[3][3] += a3 * b3;
        }
#pragma unroll
        for (int j = 0; j < 4; j++) {
            const int jj = j0 + j;
            const bool keep = (maskS[jj] != 0);
#pragma unroll
            for (int i = 0; i < 4; i++) {
                Ss[(r0 + i) * 65 + jj] = keep ? cc[i][j] : -1e9f;
            }
        }
        __syncthreads();

        // ---- phase B: online softmax + P*V ----
        float tmax = -INFINITY;
#pragma unroll
        for (int t = 0; t < 16; t++) tmax = fmaxf(tmax, Ss[row * 65 + cbase + t]);
        tmax = fmaxf(tmax, __shfl_xor_sync(0xffffffffu, tmax, 1));
        tmax = fmaxf(tmax, __shfl_xor_sync(0xffffffffu, tmax, 2));

        const float m_new = fmaxf(mval, tmax);
        const float alpha = __expf(mval - m_new);

        float psum = 0.f;
#pragma unroll
        for (int t = 0; t < 16; t++) {
            float p = __expf(Ss[row * 65 + cbase + t] - m_new);
            Ss[row * 65 + cbase + t] = p;
            psum += p;
        }
        psum += __shfl_xor_sync(0xffffffffu, psum, 1);
        psum += __shfl_xor_sync(0xffffffffu, psum, 2);
        lval = lval * alpha + psum;
        mval = m_new;

#pragma unroll
        for (int c = 0; c < 16; c++) o[c] *= alpha;
        __syncwarp();

#pragma unroll 8
        for (int j = 0; j < 64; j++) {
            const float p = Ss[row * 65 + j];
            const float* vrow = &Vs[j * 64 + cbase];
            float4 v0 = *reinterpret_cast<const float4*>(vrow + 0);
            float4 v1 = *reinterpret_cast<const float4*>(vrow + 4);
            float4 v2 = *reinterpret_cast<const float4*>(vrow + 8);
            float4 v3 = *reinterpret_cast<const float4*>(vrow + 12);
            o[0] += p * v0.x;  o[1] += p * v0.y;  o[2] += p * v0.z;  o[3] += p * v0.w;
            o[4] += p * v1.x;  o[5] += p * v1.y;  o[6] += p * v1.z;  o[7] += p * v1.w;
            o[8] += p * v2.x;  o[9] += p * v2.y;  o[10] += p * v2.z; o[11] += p * v2.w;
            o[12] += p * v3.x; o[13] += p * v3.y; o[14] += p * v3.z; o[15] += p * v3.w;
        }
        __syncthreads();
    }

    // write ctx[B*S, 1024] (heads back in column blocks)
    const float inv = 1.f / lval;
    float* optr = ctx + ((size_t)(b * SEQ + q0 + row) * D_MODEL) + h * DK + cbase;
#pragma unroll
    for (int c4 = 0; c4 < 4; c4++) {
        float4 v;
        v.x = o[c4 * 4 + 0] * inv;
        v.y = o[c4 * 4 + 1] * inv;
        v.z = o[c4 * 4 + 2] * inv;
        v.w = o[c4 * 4 + 3] * inv;
        *reinterpret_cast<float4*>(optr + c4 * 4) = v;
    }
}

// ---------------------------------------------------------------------------
extern "C" void kernel_launch(void* const* d_in, const int* in_sizes, int n_in,
                              void* d_out, int out_size)
{
    const float* q    = (const float*)d_in[0];
    const float* k    = (const float*)d_in[1];
    const float* v    = (const float*)d_in[2];
    const int*   mask = (const int*)  d_in[3];
    const float* Wq   = (const float*)d_in[4];
    const float* bq   = (const float*)d_in[5];
    const float* Wk   = (const float*)d_in[6];
    const float* bk   = (const float*)d_in[7];
    const float* Wv   = (const float*)d_in[8];
    const float* bv   = (const float*)d_in[9];
    const float* Wo   = (const float*)d_in[10];
    const float* bo   = (const float*)d_in[11];
    float* out = (float*)d_out;

    float *qh, *kh, *vh, *ctx;
    cudaGetSymbolAddress((void**)&qh,  g_qh);
    cudaGetSymbolAddress((void**)&kh,  g_kh);
    cudaGetSymbolAddress((void**)&vh,  g_vh);
    cudaGetSymbolAddress((void**)&ctx, g_ctx);

    dim3 gemm_grid(D_MODEL / 128, MROWS / 128);   // (8, 32)
    const float qscale = 0.125f;                   // 1/sqrt(64)

    gemm_bias_kernel<true><<<gemm_grid, 256>>>(q, Wq, bq, qh, qscale);
    gemm_bias_kernel<true><<<gemm_grid, 256>>>(k, Wk, bk, kh, 1.0f);
    gemm_bias_kernel<true><<<gemm_grid, 256>>>(v, Wv, bv, vh, 1.0f);

    // flash attention
    size_t smem_bytes = (64 * 65 * 3 + 64 * 64) * sizeof(float) + 64 * sizeof(int);
    cudaFuncSetAttribute(flash_attn_kernel,
                         cudaFuncAttributeMaxDynamicSharedMemorySize,
                         (int)smem_bytes);
    dim3 attn_grid(SEQ / 64, NUM_HEADS, BATCH);    // (32,16,2)
    flash_attn_kernel<<<attn_grid, 256, smem_bytes>>>(qh, kh, vh, mask, ctx);

    gemm_bias_kernel<false><<<gemm_grid, 256>>>(ctx, Wo, bo, out, 1.0f);
}